// round 5
// baseline (speedup 1.0000x reference)
#include <cuda_runtime.h>
#include <math.h>

// Problem constants
#define Bn  8
#define Hn  512
#define Wn  512
#define KK  5
#define NK  25      // KK*KK
#define HIDc 32
#define OC  50      // 2*NK

#define HW (Hn*Wn)

// Tile config: 32x8 pixel tile, 32x4 threads, 2 vertical pixels per thread.
#define TX 32
#define TYT 4
#define TYP 8
#define NTHREADS (TX*TYT)  // 128

// Guidance scratch: [B][3][H][W]
__device__ float g_guid[Bn * 3 * HW];

// ---------------------------------------------------------------------------
// packed f32x2 helpers (Blackwell)
// ---------------------------------------------------------------------------
__device__ __forceinline__ unsigned long long pk2(float lo, float hi) {
    unsigned long long r;
    asm("mov.b64 %0, {%1,%2};" : "=l"(r) : "f"(lo), "f"(hi));
    return r;
}
__device__ __forceinline__ unsigned long long dup2(float v) {
    unsigned long long r;
    asm("mov.b64 %0, {%1,%1};" : "=l"(r) : "f"(v));
    return r;
}
__device__ __forceinline__ unsigned long long fma2(unsigned long long a,
                                                   unsigned long long b,
                                                   unsigned long long c) {
    unsigned long long d;
    asm("fma.rn.f32x2 %0, %1, %2, %3;" : "=l"(d) : "l"(a), "l"(b), "l"(c));
    return d;
}
__device__ __forceinline__ float2 unpk(unsigned long long v) {
    float2 f;
    asm("mov.b64 {%0,%1}, %2;" : "=f"(f.x), "=f"(f.y) : "l"(v));
    return f;
}

// ---------------------------------------------------------------------------
// Kernel 1: bilinear grid-sample warp + fb + weight  -> guidance [B,3,H,W]
// ---------------------------------------------------------------------------
__global__ __launch_bounds__(256)
void guidance_kernel(const float* __restrict__ v02,
                     const float* __restrict__ v20,
                     float* __restrict__ guid)
{
    int idx = blockIdx.x * blockDim.x + threadIdx.x;
    if (idx >= Bn * HW) return;
    int x = idx % Wn;
    int y = (idx / Wn) % Hn;
    int b = idx / HW;

    const float* v02b = v02 + b * 2 * HW;
    const float* v20b = v20 + b * 2 * HW;

    float f0 = v02b[y * Wn + x];
    float f1 = v02b[HW + y * Wn + x];

    float gx = -1.0f + 2.0f * (float)x / (float)(Wn - 1);
    float gy = -1.0f + 2.0f * (float)y / (float)(Hn - 1);
    float sgx = gx + f0 / (Wn * 0.5f);
    float sgy = gy + f1 / (Hn * 0.5f);

    float ix = (sgx + 1.0f) * 0.5f * (float)(Wn - 1);
    float iy = (sgy + 1.0f) * 0.5f * (float)(Hn - 1);

    float x0f = floorf(ix);
    float y0f = floorf(iy);
    int   x0  = (int)x0f;
    int   y0  = (int)y0f;
    float wx1 = ix - x0f;
    float wy1 = iy - y0f;
    float wx0 = 1.0f - wx1;
    float wy0 = 1.0f - wy1;

    float s0 = 0.0f, s1 = 0.0f;
#pragma unroll
    for (int cy = 0; cy < 2; cy++) {
        int   yc = y0 + cy;
        float wy = cy ? wy1 : wy0;
        bool  vy = (yc >= 0) && (yc <= Hn - 1);
        int   yi = min(max(yc, 0), Hn - 1);
#pragma unroll
        for (int cx = 0; cx < 2; cx++) {
            int   xc = x0 + cx;
            float wx = cx ? wx1 : wx0;
            bool  vx = (xc >= 0) && (xc <= Wn - 1);
            int   xi = min(max(xc, 0), Wn - 1);
            float wgt = (vx && vy) ? (wx * wy) : 0.0f;
            s0 += wgt * v20b[yi * Wn + xi];
            s1 += wgt * v20b[HW + yi * Wn + xi];
        }
    }

    float fb0 = f0 + s0;
    float fb1 = f1 + s1;
    float cons = sqrtf(fb0 * fb0 + fb1 * fb1);
    float wv = expf(-cons);

    float* gb = guid + b * 3 * HW;
    gb[y * Wn + x]          = fb0;
    gb[HW + y * Wn + x]     = fb1;
    gb[2 * HW + y * Wn + x] = wv;
}

// ---------------------------------------------------------------------------
// Kernel 2: fused conv3x3(3->32)+ReLU + conv1x1(32->50) + dynamic 5x5 apply.
// 2 pixels per thread. All heavy math is FFMA2 whose weight operand comes
// DIRECTLY from interleaved-pair smem loads (no per-FMA dup MOVs).
// ---------------------------------------------------------------------------
__global__ __launch_bounds__(NTHREADS, 4)
void refine_kernel(const float* __restrict__ v02,
                   const float* __restrict__ guid,
                   const float* __restrict__ w1,
                   const float* __restrict__ b1,
                   const float* __restrict__ w2,
                   const float* __restrict__ b2,
                   float* __restrict__ out)
{
    // W1 interleaved channel pairs: sW1p[c][jp][s-pair], s=0..9 (9 real+1 pad)
    // pair s of (c,jp) = (w1[2jp][c][s], w1[2jp+1][c][s])
    __shared__ __align__(16) float sW1p[3 * 16 * 20];
    __shared__ __align__(8)  float sB1p[HIDc];          // (b1[2jp],b1[2jp+1]) pairs
    // W2 interleaved output-channel pairs: sW2p[ki][c][kk-pair], kk=0..5 (5 real+1 pad)
    // pair kk of (ki,c) = (w2[(5ki+kk)*32+c], w2[(25+5ki+kk)*32+c])
    __shared__ __align__(16) float sW2p[5 * 32 * 12];
    // Bias pairs per ki: sB2p[ki][kk-pair], kk=0..5
    __shared__ __align__(16) float sB2p[5 * 12];
    // Guidance tile with halo 1: [3][TYP+2][TX+2]
    __shared__ float sG[3 * (TYP + 2) * (TX + 2)];
    // Flow tile with halo 2: [2][TYP+4][TX+4]
    __shared__ float sF[2 * (TYP + 4) * (TX + 4)];

    const int tid = threadIdx.y * TX + threadIdx.x;
    const int bx = blockIdx.x * TX;
    const int by = blockIdx.y * TYP;
    const int b  = blockIdx.z;

    // --- stage W1 pairs ---  w1 global: [j][c][s] -> j*27 + c*9 + s
    for (int i = tid; i < 3 * 16 * 10; i += NTHREADS) {
        int s  = i % 10;
        int jp = (i / 10) % 16;
        int c  = i / 160;
        float lo = 0.0f, hi = 0.0f;
        if (s < 9) {
            lo = w1[(2 * jp) * 27 + c * 9 + s];
            hi = w1[(2 * jp + 1) * 27 + c * 9 + s];
        }
        sW1p[i * 2]     = lo;
        sW1p[i * 2 + 1] = hi;
    }
    if (tid < 16) {
        sB1p[tid * 2]     = b1[2 * tid];
        sB1p[tid * 2 + 1] = b1[2 * tid + 1];
    }
    // --- stage W2 pairs ---  w2 global: [k][c] -> k*32 + c
    for (int i = tid; i < 5 * 32 * 6; i += NTHREADS) {
        int kk = i % 6;
        int c  = (i / 6) % 32;
        int ki = i / 192;
        float lo = 0.0f, hi = 0.0f;
        if (kk < 5) {
            int k = ki * 5 + kk;
            lo = w2[k * 32 + c];
            hi = w2[(NK + k) * 32 + c];
        }
        sW2p[i * 2]     = lo;
        sW2p[i * 2 + 1] = hi;
    }
    if (tid < 30) {
        int kk = tid % 6;
        int ki = tid / 6;
        float lo = 0.0f, hi = 0.0f;
        if (kk < 5) {
            int k = ki * 5 + kk;
            lo = b2[k];
            hi = b2[NK + k];
        }
        sB2p[tid * 2]     = lo;
        sB2p[tid * 2 + 1] = hi;
    }

    // --- stage guidance tile (zero OOB = conv zero padding) ---
    const float* gb = guid + b * 3 * HW;
    const int GW = TX + 2, GH = TYP + 2;
    for (int i = tid; i < 3 * GH * GW; i += NTHREADS) {
        int c  = i / (GH * GW);
        int r  = i - c * (GH * GW);
        int yy = r / GW;
        int xx = r - yy * GW;
        int gyy = by + yy - 1;
        int gxx = bx + xx - 1;
        float v = 0.0f;
        if (gyy >= 0 && gyy < Hn && gxx >= 0 && gxx < Wn)
            v = gb[c * HW + gyy * Wn + gxx];
        sG[i] = v;
    }

    // --- stage flow tile (zero OOB = unfold zero padding) ---
    const float* fbase = v02 + b * 2 * HW;
    const int FW = TX + 4, FH = TYP + 4;
    for (int i = tid; i < 2 * FH * FW; i += NTHREADS) {
        int c  = i / (FH * FW);
        int r  = i - c * (FH * FW);
        int yy = r / FW;
        int xx = r - yy * FW;
        int gyy = by + yy - 2;
        int gxx = bx + xx - 2;
        float v = 0.0f;
        if (gyy >= 0 && gyy < Hn && gxx >= 0 && gxx < Wn)
            v = fbase[c * HW + gyy * Wn + gxx];
        sF[i] = v;
    }

    __syncthreads();

    const int lx = threadIdx.x;
    const int py = threadIdx.y * 2;   // tile-local row of pixel0 (pixel1 = py+1)

    // --- conv3x3: A0[jp] = (h[2jp],h[2jp+1]) for pixel0; A1 for pixel1 ---
    unsigned long long A0[16], A1[16];
    {
        const unsigned long long* bp = (const unsigned long long*)sB1p;
#pragma unroll
        for (int jp = 0; jp < 16; jp++) { A0[jp] = bp[jp]; A1[jp] = bp[jp]; }
    }

#pragma unroll
    for (int c = 0; c < 3; c++) {
        // duplicated guidance taps: 4 rows x 3 cols union of both pixels
        unsigned long long gd[12];
#pragma unroll
        for (int dy = 0; dy < 4; dy++)
#pragma unroll
            for (int dx = 0; dx < 3; dx++)
                gd[dy * 3 + dx] =
                    dup2(sG[c * (GH * GW) + (py + dy) * GW + (lx + dx)]);

        const float4* wv4 = (const float4*)(sW1p + c * 16 * 20);
        const unsigned long long* wv2 = (const unsigned long long*)(sW1p + c * 16 * 20);
#pragma unroll
        for (int jp = 0; jp < 16; jp++) {
#pragma unroll
            for (int q = 0; q < 4; q++) {          // pairs s=2q, 2q+1
                float4 w = wv4[jp * 5 + q];
                unsigned long long wp0 = pk2(w.x, w.y);
                unsigned long long wp1 = pk2(w.z, w.w);
                int s0 = 2 * q, s1 = 2 * q + 1;
                A0[jp] = fma2(wp0, gd[s0], A0[jp]);
                A1[jp] = fma2(wp0, gd[s0 + 3], A1[jp]);
                A0[jp] = fma2(wp1, gd[s1], A0[jp]);
                A1[jp] = fma2(wp1, gd[s1 + 3], A1[jp]);
            }
            {   // pair s=8 (64-bit load)
                unsigned long long wp = wv2[jp * 10 + 8];
                A0[jp] = fma2(wp, gd[8], A0[jp]);
                A1[jp] = fma2(wp, gd[11], A1[jp]);
            }
        }
    }

    // ReLU + unpack hidden vectors to scalars
    float h0[HIDc], h1[HIDc];
#pragma unroll
    for (int jp = 0; jp < 16; jp++) {
        float2 a = unpk(A0[jp]);
        h0[2 * jp]     = fmaxf(a.x, 0.0f);
        h0[2 * jp + 1] = fmaxf(a.y, 0.0f);
        float2 bb = unpk(A1[jp]);
        h1[2 * jp]     = fmaxf(bb.x, 0.0f);
        h1[2 * jp + 1] = fmaxf(bb.y, 0.0f);
    }

    // --- 1x1 conv + dynamic-kernel apply, loops swapped ---
    // out_ch(px) = sum_k b2[k] p_k + sum_c h[c] * sum_k w2[k,c] p_k
    // Accumulators packed over OUTPUT CHANNELS: O = (out_ch0, out_ch1).
    unsigned long long O0 = 0ull, O1 = 0ull;

#pragma unroll 1
    for (int ki = 0; ki < KK; ki++) {
        // flow patches packed over flow channels: pp[kj] = (flow0, flow1)
        unsigned long long pp0[5], pp1[5];
#pragma unroll
        for (int kj = 0; kj < KK; kj++) {
            pp0[kj] = pk2(sF[0 * (FH * FW) + (py + ki) * FW + (lx + kj)],
                          sF[1 * (FH * FW) + (py + ki) * FW + (lx + kj)]);
            pp1[kj] = pk2(sF[0 * (FH * FW) + (py + 1 + ki) * FW + (lx + kj)],
                          sF[1 * (FH * FW) + (py + 1 + ki) * FW + (lx + kj)]);
        }

        // bias contribution
        {
            const float4* bv = (const float4*)(sB2p + ki * 12);
            float4 bA = bv[0];   // pairs kk=0,1
            float4 bB = bv[1];   // pairs kk=2,3
            float4 bC = bv[2];   // pairs kk=4,pad
            unsigned long long p01 = pk2(bA.x, bA.y), p23 = pk2(bA.z, bA.w);
            unsigned long long p45 = pk2(bB.x, bB.y), p67 = pk2(bB.z, bB.w);
            unsigned long long p89 = pk2(bC.x, bC.y);
            O0 = fma2(p01, pp0[0], O0); O1 = fma2(p01, pp1[0], O1);
            O0 = fma2(p23, pp0[1], O0); O1 = fma2(p23, pp1[1], O1);
            O0 = fma2(p45, pp0[2], O0); O1 = fma2(p45, pp1[2], O1);
            O0 = fma2(p67, pp0[3], O0); O1 = fma2(p67, pp1[3], O1);
            O0 = fma2(p89, pp0[4], O0); O1 = fma2(p89, pp1[4], O1);
        }

        const float4* wv = (const float4*)(sW2p + ki * 32 * 12);
#pragma unroll
        for (int c = 0; c < HIDc; c++) {
            float4 wA = wv[c * 3 + 0];   // pairs kk=0,1
            float4 wB = wv[c * 3 + 1];   // pairs kk=2,3
            float4 wC = wv[c * 3 + 2];   // pairs kk=4,pad
            unsigned long long w01 = pk2(wA.x, wA.y), w23 = pk2(wA.z, wA.w);
            unsigned long long w45 = pk2(wB.x, wB.y), w67 = pk2(wB.z, wB.w);
            unsigned long long w89 = pk2(wC.x, wC.y);

            unsigned long long t0 = fma2(w01, pp0[0], 0ull);
            unsigned long long t1 = fma2(w01, pp1[0], 0ull);
            t0 = fma2(w23, pp0[1], t0);
            t1 = fma2(w23, pp1[1], t1);
            t0 = fma2(w45, pp0[2], t0);
            t1 = fma2(w45, pp1[2], t1);
            t0 = fma2(w67, pp0[3], t0);
            t1 = fma2(w67, pp1[3], t1);
            t0 = fma2(w89, pp0[4], t0);
            t1 = fma2(w89, pp1[4], t1);

            O0 = fma2(dup2(h0[c]), t0, O0);
            O1 = fma2(dup2(h1[c]), t1, O1);
        }
    }

    float2 o0 = unpk(O0);   // (ch0, ch1) for pixel0
    float2 o1 = unpk(O1);   // (ch0, ch1) for pixel1
    int oy = by + py;
    int ox = bx + lx;
    float* ob = out + b * 2 * HW;
    ob[oy * Wn + ox]            = o0.x;
    ob[HW + oy * Wn + ox]       = o0.y;
    ob[(oy + 1) * Wn + ox]      = o1.x;
    ob[HW + (oy + 1) * Wn + ox] = o1.y;
}

// ---------------------------------------------------------------------------
// Launch
// ---------------------------------------------------------------------------
extern "C" void kernel_launch(void* const* d_in, const int* in_sizes, int n_in,
                              void* d_out, int out_size)
{
    const float* v02 = (const float*)d_in[0];
    const float* v20 = (const float*)d_in[1];
    const float* w1  = (const float*)d_in[2];
    const float* b1  = (const float*)d_in[3];
    const float* w2  = (const float*)d_in[4];
    const float* b2  = (const float*)d_in[5];
    float* out = (float*)d_out;

    float* guid;
    cudaGetSymbolAddress((void**)&guid, g_guid);

    {
        int total = Bn * HW;
        int threads = 256;
        int blocks = (total + threads - 1) / threads;
        guidance_kernel<<<blocks, threads>>>(v02, v20, guid);
    }
    {
        dim3 block(TX, TYT, 1);
        dim3 grid(Wn / TX, Hn / TYP, Bn);
        refine_kernel<<<grid, block>>>(v02, guid, w1, b1, w2, b2, out);
    }
}

// round 7
// speedup vs baseline: 1.0010x; 1.0010x over previous
#include <cuda_runtime.h>
#include <math.h>

// Problem constants
#define Bn  8
#define Hn  512
#define Wn  512
#define KK  5
#define NK  25      // KK*KK
#define HIDc 32
#define OC  50      // 2*NK

#define HW (Hn*Wn)

// Tile config: 32x8 pixel tile, 32x4 threads, 2 vertical pixels per thread.
#define TX 32
#define TYT 4
#define TYP 8
#define NTHREADS (TX*TYT)  // 128

// Guidance scratch: [B][3][H][W]
__device__ float g_guid[Bn * 3 * HW];

// ---------------------------------------------------------------------------
// packed f32x2 helpers (Blackwell)
// ---------------------------------------------------------------------------
__device__ __forceinline__ unsigned long long pk2(float lo, float hi) {
    unsigned long long r;
    asm("mov.b64 %0, {%1,%2};" : "=l"(r) : "f"(lo), "f"(hi));
    return r;
}
__device__ __forceinline__ unsigned long long dup2(float v) {
    unsigned long long r;
    asm("mov.b64 %0, {%1,%1};" : "=l"(r) : "f"(v));
    return r;
}
__device__ __forceinline__ unsigned long long fma2(unsigned long long a,
                                                   unsigned long long b,
                                                   unsigned long long c) {
    unsigned long long d;
    asm("fma.rn.f32x2 %0, %1, %2, %3;" : "=l"(d) : "l"(a), "l"(b), "l"(c));
    return d;
}
__device__ __forceinline__ float2 unpk(unsigned long long v) {
    float2 f;
    asm("mov.b64 {%0,%1}, %2;" : "=f"(f.x), "=f"(f.y) : "l"(v));
    return f;
}

// ---------------------------------------------------------------------------
// Kernel 1: bilinear grid-sample warp + fb + weight  -> guidance [B,3,H,W]
// ---------------------------------------------------------------------------
__global__ __launch_bounds__(256)
void guidance_kernel(const float* __restrict__ v02,
                     const float* __restrict__ v20,
                     float* __restrict__ guid)
{
    int idx = blockIdx.x * blockDim.x + threadIdx.x;
    if (idx >= Bn * HW) return;
    int x = idx % Wn;
    int y = (idx / Wn) % Hn;
    int b = idx / HW;

    const float* v02b = v02 + b * 2 * HW;
    const float* v20b = v20 + b * 2 * HW;

    float f0 = v02b[y * Wn + x];
    float f1 = v02b[HW + y * Wn + x];

    float gx = -1.0f + 2.0f * (float)x / (float)(Wn - 1);
    float gy = -1.0f + 2.0f * (float)y / (float)(Hn - 1);
    float sgx = gx + f0 / (Wn * 0.5f);
    float sgy = gy + f1 / (Hn * 0.5f);

    float ix = (sgx + 1.0f) * 0.5f * (float)(Wn - 1);
    float iy = (sgy + 1.0f) * 0.5f * (float)(Hn - 1);

    float x0f = floorf(ix);
    float y0f = floorf(iy);
    int   x0  = (int)x0f;
    int   y0  = (int)y0f;
    float wx1 = ix - x0f;
    float wy1 = iy - y0f;
    float wx0 = 1.0f - wx1;
    float wy0 = 1.0f - wy1;

    float s0 = 0.0f, s1 = 0.0f;
#pragma unroll
    for (int cy = 0; cy < 2; cy++) {
        int   yc = y0 + cy;
        float wy = cy ? wy1 : wy0;
        bool  vy = (yc >= 0) && (yc <= Hn - 1);
        int   yi = min(max(yc, 0), Hn - 1);
#pragma unroll
        for (int cx = 0; cx < 2; cx++) {
            int   xc = x0 + cx;
            float wx = cx ? wx1 : wx0;
            bool  vx = (xc >= 0) && (xc <= Wn - 1);
            int   xi = min(max(xc, 0), Wn - 1);
            float wgt = (vx && vy) ? (wx * wy) : 0.0f;
            s0 += wgt * v20b[yi * Wn + xi];
            s1 += wgt * v20b[HW + yi * Wn + xi];
        }
    }

    float fb0 = f0 + s0;
    float fb1 = f1 + s1;
    float cons = sqrtf(fb0 * fb0 + fb1 * fb1);
    float wv = expf(-cons);

    float* gb = guid + b * 3 * HW;
    gb[y * Wn + x]          = fb0;
    gb[HW + y * Wn + x]     = fb1;
    gb[2 * HW + y * Wn + x] = wv;
}

// ---------------------------------------------------------------------------
// Kernel 2: fused conv3x3(3->32)+ReLU + conv1x1(32->50) + dynamic 5x5 apply.
// 2 pixels per thread. All heavy math is FFMA2 whose weight operand comes
// DIRECTLY from interleaved-pair smem loads (no per-FMA dup MOVs).
// ---------------------------------------------------------------------------
__global__ __launch_bounds__(NTHREADS, 4)
void refine_kernel(const float* __restrict__ v02,
                   const float* __restrict__ guid,
                   const float* __restrict__ w1,
                   const float* __restrict__ b1,
                   const float* __restrict__ w2,
                   const float* __restrict__ b2,
                   float* __restrict__ out)
{
    // W1 interleaved channel pairs: sW1p[c][jp][s-pair], s=0..9 (9 real+1 pad)
    // pair s of (c,jp) = (w1[2jp][c][s], w1[2jp+1][c][s])
    __shared__ __align__(16) float sW1p[3 * 16 * 20];
    __shared__ __align__(8)  float sB1p[HIDc];          // (b1[2jp],b1[2jp+1]) pairs
    // W2 interleaved output-channel pairs: sW2p[ki][c][kk-pair], kk=0..5 (5 real+1 pad)
    // pair kk of (ki,c) = (w2[(5ki+kk)*32+c], w2[(25+5ki+kk)*32+c])
    __shared__ __align__(16) float sW2p[5 * 32 * 12];
    // Bias pairs per ki: sB2p[ki][kk-pair], kk=0..5
    __shared__ __align__(16) float sB2p[5 * 12];
    // Guidance tile with halo 1: [3][TYP+2][TX+2]
    __shared__ float sG[3 * (TYP + 2) * (TX + 2)];
    // Flow tile with halo 2: [2][TYP+4][TX+4]
    __shared__ float sF[2 * (TYP + 4) * (TX + 4)];

    const int tid = threadIdx.y * TX + threadIdx.x;
    const int bx = blockIdx.x * TX;
    const int by = blockIdx.y * TYP;
    const int b  = blockIdx.z;

    // --- stage W1 pairs ---  w1 global: [j][c][s] -> j*27 + c*9 + s
    for (int i = tid; i < 3 * 16 * 10; i += NTHREADS) {
        int s  = i % 10;
        int jp = (i / 10) % 16;
        int c  = i / 160;
        float lo = 0.0f, hi = 0.0f;
        if (s < 9) {
            lo = w1[(2 * jp) * 27 + c * 9 + s];
            hi = w1[(2 * jp + 1) * 27 + c * 9 + s];
        }
        sW1p[i * 2]     = lo;
        sW1p[i * 2 + 1] = hi;
    }
    if (tid < 16) {
        sB1p[tid * 2]     = b1[2 * tid];
        sB1p[tid * 2 + 1] = b1[2 * tid + 1];
    }
    // --- stage W2 pairs ---  w2 global: [k][c] -> k*32 + c
    for (int i = tid; i < 5 * 32 * 6; i += NTHREADS) {
        int kk = i % 6;
        int c  = (i / 6) % 32;
        int ki = i / 192;
        float lo = 0.0f, hi = 0.0f;
        if (kk < 5) {
            int k = ki * 5 + kk;
            lo = w2[k * 32 + c];
            hi = w2[(NK + k) * 32 + c];
        }
        sW2p[i * 2]     = lo;
        sW2p[i * 2 + 1] = hi;
    }
    if (tid < 30) {
        int kk = tid % 6;
        int ki = tid / 6;
        float lo = 0.0f, hi = 0.0f;
        if (kk < 5) {
            int k = ki * 5 + kk;
            lo = b2[k];
            hi = b2[NK + k];
        }
        sB2p[tid * 2]     = lo;
        sB2p[tid * 2 + 1] = hi;
    }

    // --- stage guidance tile (zero OOB = conv zero padding) ---
    const float* gb = guid + b * 3 * HW;
    const int GW = TX + 2, GH = TYP + 2;
    for (int i = tid; i < 3 * GH * GW; i += NTHREADS) {
        int c  = i / (GH * GW);
        int r  = i - c * (GH * GW);
        int yy = r / GW;
        int xx = r - yy * GW;
        int gyy = by + yy - 1;
        int gxx = bx + xx - 1;
        float v = 0.0f;
        if (gyy >= 0 && gyy < Hn && gxx >= 0 && gxx < Wn)
            v = gb[c * HW + gyy * Wn + gxx];
        sG[i] = v;
    }

    // --- stage flow tile (zero OOB = unfold zero padding) ---
    const float* fbase = v02 + b * 2 * HW;
    const int FW = TX + 4, FH = TYP + 4;
    for (int i = tid; i < 2 * FH * FW; i += NTHREADS) {
        int c  = i / (FH * FW);
        int r  = i - c * (FH * FW);
        int yy = r / FW;
        int xx = r - yy * FW;
        int gyy = by + yy - 2;
        int gxx = bx + xx - 2;
        float v = 0.0f;
        if (gyy >= 0 && gyy < Hn && gxx >= 0 && gxx < Wn)
            v = fbase[c * HW + gyy * Wn + gxx];
        sF[i] = v;
    }

    __syncthreads();

    const int lx = threadIdx.x;
    const int py = threadIdx.y * 2;   // tile-local row of pixel0 (pixel1 = py+1)

    // --- conv3x3: A0[jp] = (h[2jp],h[2jp+1]) for pixel0; A1 for pixel1 ---
    unsigned long long A0[16], A1[16];
    {
        const unsigned long long* bp = (const unsigned long long*)sB1p;
#pragma unroll
        for (int jp = 0; jp < 16; jp++) { A0[jp] = bp[jp]; A1[jp] = bp[jp]; }
    }

#pragma unroll
    for (int c = 0; c < 3; c++) {
        // duplicated guidance taps: 4 rows x 3 cols union of both pixels
        unsigned long long gd[12];
#pragma unroll
        for (int dy = 0; dy < 4; dy++)
#pragma unroll
            for (int dx = 0; dx < 3; dx++)
                gd[dy * 3 + dx] =
                    dup2(sG[c * (GH * GW) + (py + dy) * GW + (lx + dx)]);

        const float4* wv4 = (const float4*)(sW1p + c * 16 * 20);
        const unsigned long long* wv2 = (const unsigned long long*)(sW1p + c * 16 * 20);
#pragma unroll
        for (int jp = 0; jp < 16; jp++) {
#pragma unroll
            for (int q = 0; q < 4; q++) {          // pairs s=2q, 2q+1
                float4 w = wv4[jp * 5 + q];
                unsigned long long wp0 = pk2(w.x, w.y);
                unsigned long long wp1 = pk2(w.z, w.w);
                int s0 = 2 * q, s1 = 2 * q + 1;
                A0[jp] = fma2(wp0, gd[s0], A0[jp]);
                A1[jp] = fma2(wp0, gd[s0 + 3], A1[jp]);
                A0[jp] = fma2(wp1, gd[s1], A0[jp]);
                A1[jp] = fma2(wp1, gd[s1 + 3], A1[jp]);
            }
            {   // pair s=8 (64-bit load)
                unsigned long long wp = wv2[jp * 10 + 8];
                A0[jp] = fma2(wp, gd[8], A0[jp]);
                A1[jp] = fma2(wp, gd[11], A1[jp]);
            }
        }
    }

    // ReLU + unpack hidden vectors to scalars
    float h0[HIDc], h1[HIDc];
#pragma unroll
    for (int jp = 0; jp < 16; jp++) {
        float2 a = unpk(A0[jp]);
        h0[2 * jp]     = fmaxf(a.x, 0.0f);
        h0[2 * jp + 1] = fmaxf(a.y, 0.0f);
        float2 bb = unpk(A1[jp]);
        h1[2 * jp]     = fmaxf(bb.x, 0.0f);
        h1[2 * jp + 1] = fmaxf(bb.y, 0.0f);
    }

    // --- 1x1 conv + dynamic-kernel apply, loops swapped ---
    // out_ch(px) = sum_k b2[k] p_k + sum_c h[c] * sum_k w2[k,c] p_k
    // Accumulators packed over OUTPUT CHANNELS: O = (out_ch0, out_ch1).
    unsigned long long O0 = 0ull, O1 = 0ull;

#pragma unroll 1
    for (int ki = 0; ki < KK; ki++) {
        // flow patches packed over flow channels: pp[kj] = (flow0, flow1)
        unsigned long long pp0[5], pp1[5];
#pragma unroll
        for (int kj = 0; kj < KK; kj++) {
            pp0[kj] = pk2(sF[0 * (FH * FW) + (py + ki) * FW + (lx + kj)],
                          sF[1 * (FH * FW) + (py + ki) * FW + (lx + kj)]);
            pp1[kj] = pk2(sF[0 * (FH * FW) + (py + 1 + ki) * FW + (lx + kj)],
                          sF[1 * (FH * FW) + (py + 1 + ki) * FW + (lx + kj)]);
        }

        // bias contribution
        {
            const float4* bv = (const float4*)(sB2p + ki * 12);
            float4 bA = bv[0];   // pairs kk=0,1
            float4 bB = bv[1];   // pairs kk=2,3
            float4 bC = bv[2];   // pairs kk=4,pad
            unsigned long long p01 = pk2(bA.x, bA.y), p23 = pk2(bA.z, bA.w);
            unsigned long long p45 = pk2(bB.x, bB.y), p67 = pk2(bB.z, bB.w);
            unsigned long long p89 = pk2(bC.x, bC.y);
            O0 = fma2(p01, pp0[0], O0); O1 = fma2(p01, pp1[0], O1);
            O0 = fma2(p23, pp0[1], O0); O1 = fma2(p23, pp1[1], O1);
            O0 = fma2(p45, pp0[2], O0); O1 = fma2(p45, pp1[2], O1);
            O0 = fma2(p67, pp0[3], O0); O1 = fma2(p67, pp1[3], O1);
            O0 = fma2(p89, pp0[4], O0); O1 = fma2(p89, pp1[4], O1);
        }

        const float4* wv = (const float4*)(sW2p + ki * 32 * 12);
#pragma unroll
        for (int c = 0; c < HIDc; c++) {
            float4 wA = wv[c * 3 + 0];   // pairs kk=0,1
            float4 wB = wv[c * 3 + 1];   // pairs kk=2,3
            float4 wC = wv[c * 3 + 2];   // pairs kk=4,pad
            unsigned long long w01 = pk2(wA.x, wA.y), w23 = pk2(wA.z, wA.w);
            unsigned long long w45 = pk2(wB.x, wB.y), w67 = pk2(wB.z, wB.w);
            unsigned long long w89 = pk2(wC.x, wC.y);

            unsigned long long t0 = fma2(w01, pp0[0], 0ull);
            unsigned long long t1 = fma2(w01, pp1[0], 0ull);
            t0 = fma2(w23, pp0[1], t0);
            t1 = fma2(w23, pp1[1], t1);
            t0 = fma2(w45, pp0[2], t0);
            t1 = fma2(w45, pp1[2], t1);
            t0 = fma2(w67, pp0[3], t0);
            t1 = fma2(w67, pp1[3], t1);
            t0 = fma2(w89, pp0[4], t0);
            t1 = fma2(w89, pp1[4], t1);

            O0 = fma2(dup2(h0[c]), t0, O0);
            O1 = fma2(dup2(h1[c]), t1, O1);
        }
    }

    float2 o0 = unpk(O0);   // (ch0, ch1) for pixel0
    float2 o1 = unpk(O1);   // (ch0, ch1) for pixel1
    int oy = by + py;
    int ox = bx + lx;
    float* ob = out + b * 2 * HW;
    ob[oy * Wn + ox]            = o0.x;
    ob[HW + oy * Wn + ox]       = o0.y;
    ob[(oy + 1) * Wn + ox]      = o1.x;
    ob[HW + (oy + 1) * Wn + ox] = o1.y;
}

// ---------------------------------------------------------------------------
// Launch
// ---------------------------------------------------------------------------
extern "C" void kernel_launch(void* const* d_in, const int* in_sizes, int n_in,
                              void* d_out, int out_size)
{
    const float* v02 = (const float*)d_in[0];
    const float* v20 = (const float*)d_in[1];
    const float* w1  = (const float*)d_in[2];
    const float* b1  = (const float*)d_in[3];
    const float* w2  = (const float*)d_in[4];
    const float* b2  = (const float*)d_in[5];
    float* out = (float*)d_out;

    float* guid;
    cudaGetSymbolAddress((void**)&guid, g_guid);

    {
        int total = Bn * HW;
        int threads = 256;
        int blocks = (total + threads - 1) / threads;
        guidance_kernel<<<blocks, threads>>>(v02, v20, guid);
    }
    {
        dim3 block(TX, TYT, 1);
        dim3 grid(Wn / TX, Hn / TYP, Bn);
        refine_kernel<<<grid, block>>>(v02, guid, w1, b1, w2, b2, out);
    }
}

// round 8
// speedup vs baseline: 1.0079x; 1.0068x over previous
#include <cuda_runtime.h>
#include <math.h>
#include <string.h>

// Problem constants
#define Bn  8
#define Hn  512
#define Wn  512
#define KK  5
#define NK  25      // KK*KK
#define HIDc 32
#define OC  50      // 2*NK

#define HW (Hn*Wn)

// Tile config: 32x8 pixel tile, 32x4 threads, 2 vertical pixels per thread.
#define TX 32
#define TYT 4
#define TYP 8
#define NTHREADS (TX*TYT)  // 128

#define GW (TX + 2)
#define GH (TYP + 2)
#define FW (TX + 4)
#define FH (TYP + 4)

// Guidance scratch: [B][3][H][W]
__device__ float g_guid[Bn * 3 * HW];

typedef unsigned long long u64;

// ---------------------------------------------------------------------------
// packed f32x2 helpers
// ---------------------------------------------------------------------------
__device__ __forceinline__ u64 pk2(float lo, float hi) {
    u64 r;
    asm("mov.b64 %0, {%1,%2};" : "=l"(r) : "f"(lo), "f"(hi));
    return r;
}
__device__ __forceinline__ u64 fma2(u64 a, u64 b, u64 c) {
    u64 d;
    asm("fma.rn.f32x2 %0, %1, %2, %3;" : "=l"(d) : "l"(a), "l"(b), "l"(c));
    return d;
}
// MOV-free reinterpret of a 64-bit pair as two floats
__device__ __forceinline__ float2 as_f2(u64 v) {
    float2 f;
    memcpy(&f, &v, 8);
    return f;
}

// ---------------------------------------------------------------------------
// Kernel 1: bilinear grid-sample warp + fb + weight  -> guidance [B,3,H,W]
// ---------------------------------------------------------------------------
__global__ __launch_bounds__(256)
void guidance_kernel(const float* __restrict__ v02,
                     const float* __restrict__ v20,
                     float* __restrict__ guid)
{
    int idx = blockIdx.x * blockDim.x + threadIdx.x;
    if (idx >= Bn * HW) return;
    int x = idx % Wn;
    int y = (idx / Wn) % Hn;
    int b = idx / HW;

    const float* v02b = v02 + b * 2 * HW;
    const float* v20b = v20 + b * 2 * HW;

    float f0 = v02b[y * Wn + x];
    float f1 = v02b[HW + y * Wn + x];

    float gx = -1.0f + 2.0f * (float)x / (float)(Wn - 1);
    float gy = -1.0f + 2.0f * (float)y / (float)(Hn - 1);
    float sgx = gx + f0 / (Wn * 0.5f);
    float sgy = gy + f1 / (Hn * 0.5f);

    float ix = (sgx + 1.0f) * 0.5f * (float)(Wn - 1);
    float iy = (sgy + 1.0f) * 0.5f * (float)(Hn - 1);

    float x0f = floorf(ix);
    float y0f = floorf(iy);
    int   x0  = (int)x0f;
    int   y0  = (int)y0f;
    float wx1 = ix - x0f;
    float wy1 = iy - y0f;
    float wx0 = 1.0f - wx1;
    float wy0 = 1.0f - wy1;

    float s0 = 0.0f, s1 = 0.0f;
#pragma unroll
    for (int cy = 0; cy < 2; cy++) {
        int   yc = y0 + cy;
        float wy = cy ? wy1 : wy0;
        bool  vy = (yc >= 0) && (yc <= Hn - 1);
        int   yi = min(max(yc, 0), Hn - 1);
#pragma unroll
        for (int cx = 0; cx < 2; cx++) {
            int   xc = x0 + cx;
            float wx = cx ? wx1 : wx0;
            bool  vx = (xc >= 0) && (xc <= Wn - 1);
            int   xi = min(max(xc, 0), Wn - 1);
            float wgt = (vx && vy) ? (wx * wy) : 0.0f;
            s0 += wgt * v20b[yi * Wn + xi];
            s1 += wgt * v20b[HW + yi * Wn + xi];
        }
    }

    float fb0 = f0 + s0;
    float fb1 = f1 + s1;
    float cons = sqrtf(fb0 * fb0 + fb1 * fb1);
    float wv = expf(-cons);

    float* gb = guid + b * 3 * HW;
    gb[y * Wn + x]          = fb0;
    gb[HW + y * Wn + x]     = fb1;
    gb[2 * HW + y * Wn + x] = wv;
}

// ---------------------------------------------------------------------------
// Kernel 2: fused conv3x3(3->32)+ReLU + conv1x1(32->50) + dynamic 5x5 apply.
// 2 pixels per thread. All fma2 operands come MOV-free from smem:
//  - weights: interleaved pairs loaded as ulonglong2 / u64
//  - guidance taps: pre-duplicated (g,g) pairs in smem
//  - flow patches: pre-channel-paired (f0,f1) in smem
// Tail products use scalar FFMA reading register-pair halves (no dup MOVs).
// ---------------------------------------------------------------------------
__global__ __launch_bounds__(NTHREADS, 4)
void refine_kernel(const float* __restrict__ v02,
                   const float* __restrict__ guid,
                   const float* __restrict__ w1,
                   const float* __restrict__ b1,
                   const float* __restrict__ w2,
                   const float* __restrict__ b2,
                   float* __restrict__ out)
{
    // W1 interleaved channel pairs: [c][jp][10 s-pairs]; pair s = (w1[2jp][c][s], w1[2jp+1][c][s])
    __shared__ __align__(16) float sW1p[3 * 16 * 20];
    __shared__ __align__(8)  float sB1p[HIDc];          // (b1[2jp],b1[2jp+1])
    // W2 interleaved output-channel pairs: [ki][c][6 kk-pairs]; pair kk = (w2[5ki+kk][c], w2[25+5ki+kk][c])
    __shared__ __align__(16) float sW2p[5 * 32 * 12];
    __shared__ __align__(16) float sB2p[5 * 12];
    // Guidance tile, DUPLICATED pairs (g,g): [3][GH][GW]
    __shared__ __align__(8) u64 sGp[3 * GH * GW];
    // Flow tile, channel pairs (flow0,flow1): [FH][FW]
    __shared__ __align__(8) u64 sFp[FH * FW];

    const int tid = threadIdx.y * TX + threadIdx.x;
    const int bx = blockIdx.x * TX;
    const int by = blockIdx.y * TYP;
    const int b  = blockIdx.z;

    // --- stage W1 pairs ---  w1 global: [j][c][s] -> j*27 + c*9 + s
    for (int i = tid; i < 3 * 16 * 10; i += NTHREADS) {
        int s  = i % 10;
        int jp = (i / 10) % 16;
        int c  = i / 160;
        float lo = 0.0f, hi = 0.0f;
        if (s < 9) {
            lo = w1[(2 * jp) * 27 + c * 9 + s];
            hi = w1[(2 * jp + 1) * 27 + c * 9 + s];
        }
        sW1p[i * 2]     = lo;
        sW1p[i * 2 + 1] = hi;
    }
    if (tid < 16) {
        sB1p[tid * 2]     = b1[2 * tid];
        sB1p[tid * 2 + 1] = b1[2 * tid + 1];
    }
    // --- stage W2 pairs ---  w2 global: [k][c] -> k*32 + c
    for (int i = tid; i < 5 * 32 * 6; i += NTHREADS) {
        int kk = i % 6;
        int c  = (i / 6) % 32;
        int ki = i / 192;
        float lo = 0.0f, hi = 0.0f;
        if (kk < 5) {
            int k = ki * 5 + kk;
            lo = w2[k * 32 + c];
            hi = w2[(NK + k) * 32 + c];
        }
        sW2p[i * 2]     = lo;
        sW2p[i * 2 + 1] = hi;
    }
    if (tid < 30) {
        int kk = tid % 6;
        int ki = tid / 6;
        float lo = 0.0f, hi = 0.0f;
        if (kk < 5) {
            int k = ki * 5 + kk;
            lo = b2[k];
            hi = b2[NK + k];
        }
        sB2p[tid * 2]     = lo;
        sB2p[tid * 2 + 1] = hi;
    }

    // --- stage guidance tile as duplicated pairs (zero OOB = conv padding) ---
    const float* gb = guid + b * 3 * HW;
    for (int i = tid; i < 3 * GH * GW; i += NTHREADS) {
        int c  = i / (GH * GW);
        int r  = i - c * (GH * GW);
        int yy = r / GW;
        int xx = r - yy * GW;
        int gyy = by + yy - 1;
        int gxx = bx + xx - 1;
        float v = 0.0f;
        if (gyy >= 0 && gyy < Hn && gxx >= 0 && gxx < Wn)
            v = gb[c * HW + gyy * Wn + gxx];
        sGp[i] = pk2(v, v);
    }

    // --- stage flow tile as channel pairs (zero OOB = unfold padding) ---
    const float* fbase = v02 + b * 2 * HW;
    for (int i = tid; i < FH * FW; i += NTHREADS) {
        int yy = i / FW;
        int xx = i - yy * FW;
        int gyy = by + yy - 2;
        int gxx = bx + xx - 2;
        float f0 = 0.0f, f1 = 0.0f;
        if (gyy >= 0 && gyy < Hn && gxx >= 0 && gxx < Wn) {
            f0 = fbase[gyy * Wn + gxx];
            f1 = fbase[HW + gyy * Wn + gxx];
        }
        sFp[i] = pk2(f0, f1);
    }

    __syncthreads();

    const int lx = threadIdx.x;
    const int py = threadIdx.y * 2;   // tile-local row of pixel0 (pixel1 = py+1)

    // --- conv3x3: A0[jp] = (h[2jp],h[2jp+1]) for pixel0; A1 for pixel1 ---
    u64 A0[16], A1[16];
    {
        const u64* bp = (const u64*)sB1p;
#pragma unroll
        for (int jp = 0; jp < 16; jp++) { A0[jp] = bp[jp]; A1[jp] = bp[jp]; }
    }

#pragma unroll
    for (int c = 0; c < 3; c++) {
        // duplicated taps: 4 rows x 3 cols union of both pixels (direct LDS.64)
        u64 gd[12];
#pragma unroll
        for (int dy = 0; dy < 4; dy++)
#pragma unroll
            for (int dx = 0; dx < 3; dx++)
                gd[dy * 3 + dx] = sGp[c * (GH * GW) + (py + dy) * GW + (lx + dx)];

#pragma unroll
        for (int jp = 0; jp < 16; jp++) {
            const float* base = sW1p + (c * 16 + jp) * 20;
            ulonglong2 wA = *(const ulonglong2*)(base);        // s0,s1
            ulonglong2 wB = *(const ulonglong2*)(base + 4);    // s2,s3
            ulonglong2 wC = *(const ulonglong2*)(base + 8);    // s4,s5
            ulonglong2 wD = *(const ulonglong2*)(base + 12);   // s6,s7
            u64        wE = *(const u64*)(base + 16);          // s8
            A0[jp] = fma2(wA.x, gd[0], A0[jp]);  A1[jp] = fma2(wA.x, gd[3], A1[jp]);
            A0[jp] = fma2(wA.y, gd[1], A0[jp]);  A1[jp] = fma2(wA.y, gd[4], A1[jp]);
            A0[jp] = fma2(wB.x, gd[2], A0[jp]);  A1[jp] = fma2(wB.x, gd[5], A1[jp]);
            A0[jp] = fma2(wB.y, gd[3], A0[jp]);  A1[jp] = fma2(wB.y, gd[6], A1[jp]);
            A0[jp] = fma2(wC.x, gd[4], A0[jp]);  A1[jp] = fma2(wC.x, gd[7], A1[jp]);
            A0[jp] = fma2(wC.y, gd[5], A0[jp]);  A1[jp] = fma2(wC.y, gd[8], A1[jp]);
            A0[jp] = fma2(wD.x, gd[6], A0[jp]);  A1[jp] = fma2(wD.x, gd[9], A1[jp]);
            A0[jp] = fma2(wD.y, gd[7], A0[jp]);  A1[jp] = fma2(wD.y, gd[10], A1[jp]);
            A0[jp] = fma2(wE,   gd[8], A0[jp]);  A1[jp] = fma2(wE,   gd[11], A1[jp]);
        }
    }

    // ReLU; h scalars alias the A register-pair halves (A dead after)
    float h0f[HIDc], h1f[HIDc];
#pragma unroll
    for (int jp = 0; jp < 16; jp++) {
        float2 a = as_f2(A0[jp]);
        h0f[2 * jp]     = fmaxf(a.x, 0.0f);
        h0f[2 * jp + 1] = fmaxf(a.y, 0.0f);
        float2 bb = as_f2(A1[jp]);
        h1f[2 * jp]     = fmaxf(bb.x, 0.0f);
        h1f[2 * jp + 1] = fmaxf(bb.y, 0.0f);
    }

    // --- 1x1 conv + dynamic-kernel apply (loops swapped):
    // out_ch(px) = sum_k b2[k] p_k + sum_c h[c] * (sum_k w2[k,c] p_k)
    float oc0p0 = 0.0f, oc1p0 = 0.0f;   // pixel0: ch0, ch1
    float oc0p1 = 0.0f, oc1p1 = 0.0f;   // pixel1: ch0, ch1

#pragma unroll 1
    for (int ki = 0; ki < KK; ki++) {
        // patch pairs (flow0,flow1), direct LDS.64
        u64 pp0[5], pp1[5];
#pragma unroll
        for (int kj = 0; kj < KK; kj++) {
            pp0[kj] = sFp[(py + ki) * FW + (lx + kj)];
            pp1[kj] = sFp[(py + 1 + ki) * FW + (lx + kj)];
        }

        // bias contribution (acts like an extra channel with h = 1)
        {
            const float* base = sB2p + ki * 12;
            ulonglong2 b01 = *(const ulonglong2*)(base);
            ulonglong2 b23 = *(const ulonglong2*)(base + 4);
            u64        b4  = *(const u64*)(base + 8);
            u64 t0 = fma2(b01.x, pp0[0], 0ull);
            u64 t1 = fma2(b01.x, pp1[0], 0ull);
            t0 = fma2(b01.y, pp0[1], t0);  t1 = fma2(b01.y, pp1[1], t1);
            t0 = fma2(b23.x, pp0[2], t0);  t1 = fma2(b23.x, pp1[2], t1);
            t0 = fma2(b23.y, pp0[3], t0);  t1 = fma2(b23.y, pp1[3], t1);
            t0 = fma2(b4,    pp0[4], t0);  t1 = fma2(b4,    pp1[4], t1);
            float2 a = as_f2(t0), bb = as_f2(t1);
            oc0p0 += a.x;  oc1p0 += a.y;
            oc0p1 += bb.x; oc1p1 += bb.y;
        }

#pragma unroll
        for (int c = 0; c < HIDc; c++) {
            const float* base = sW2p + (ki * 32 + c) * 12;
            ulonglong2 w01 = *(const ulonglong2*)(base);       // kk pairs 0,1
            ulonglong2 w23 = *(const ulonglong2*)(base + 4);   // kk pairs 2,3
            u64        w4  = *(const u64*)(base + 8);          // kk pair 4

            u64 t0 = fma2(w01.x, pp0[0], 0ull);
            u64 t1 = fma2(w01.x, pp1[0], 0ull);
            t0 = fma2(w01.y, pp0[1], t0);  t1 = fma2(w01.y, pp1[1], t1);
            t0 = fma2(w23.x, pp0[2], t0);  t1 = fma2(w23.x, pp1[2], t1);
            t0 = fma2(w23.y, pp0[3], t0);  t1 = fma2(w23.y, pp1[3], t1);
            t0 = fma2(w4,    pp0[4], t0);  t1 = fma2(w4,    pp1[4], t1);

            float2 a = as_f2(t0), bb = as_f2(t1);
            oc0p0 = fmaf(h0f[c], a.x, oc0p0);
            oc1p0 = fmaf(h0f[c], a.y, oc1p0);
            oc0p1 = fmaf(h1f[c], bb.x, oc0p1);
            oc1p1 = fmaf(h1f[c], bb.y, oc1p1);
        }
    }

    int oy = by + py;
    int ox = bx + lx;
    float* ob = out + b * 2 * HW;
    ob[oy * Wn + ox]            = oc0p0;
    ob[HW + oy * Wn + ox]       = oc1p0;
    ob[(oy + 1) * Wn + ox]      = oc0p1;
    ob[HW + (oy + 1) * Wn + ox] = oc1p1;
}

// ---------------------------------------------------------------------------
// Launch
// ---------------------------------------------------------------------------
extern "C" void kernel_launch(void* const* d_in, const int* in_sizes, int n_in,
                              void* d_out, int out_size)
{
    const float* v02 = (const float*)d_in[0];
    const float* v20 = (const float*)d_in[1];
    const float* w1  = (const float*)d_in[2];
    const float* b1  = (const float*)d_in[3];
    const float* w2  = (const float*)d_in[4];
    const float* b2  = (const float*)d_in[5];
    float* out = (float*)d_out;

    float* guid;
    cudaGetSymbolAddress((void**)&guid, g_guid);

    {
        int total = Bn * HW;
        int threads = 256;
        int blocks = (total + threads - 1) / threads;
        guidance_kernel<<<blocks, threads>>>(v02, v20, guid);
    }
    {
        dim3 block(TX, TYT, 1);
        dim3 grid(Wn / TX, Hn / TYP, Bn);
        refine_kernel<<<grid, block>>>(v02, guid, w1, b1, w2, b2, out);
    }
}

// round 9
// speedup vs baseline: 1.2201x; 1.2106x over previous
#include <cuda_runtime.h>
#include <math.h>
#include <string.h>

// Problem constants
#define Bn  8
#define Hn  512
#define Wn  512
#define KK  5
#define NK  25      // KK*KK
#define HIDc 32
#define OC  50      // 2*NK

#define HW (Hn*Wn)

// Tile config: 32x8 pixel tile, 32x4 threads, 2 vertical pixels per thread.
#define TX 32
#define TYT 4
#define TYP 8
#define NTHREADS (TX*TYT)  // 128

#define GW (TX + 2)
#define GH (TYP + 2)
#define FW (TX + 4)
#define FH (TYP + 4)

// Guidance scratch: [B][3][H][W]
__device__ float g_guid[Bn * 3 * HW];

typedef unsigned long long u64;

// ---------------------------------------------------------------------------
// packed f32x2 helpers
// ---------------------------------------------------------------------------
__device__ __forceinline__ u64 pk2(float lo, float hi) {
    u64 r;
    asm("mov.b64 %0, {%1,%2};" : "=l"(r) : "f"(lo), "f"(hi));
    return r;
}
__device__ __forceinline__ u64 fma2(u64 a, u64 b, u64 c) {
    u64 d;
    asm("fma.rn.f32x2 %0, %1, %2, %3;" : "=l"(d) : "l"(a), "l"(b), "l"(c));
    return d;
}
// MOV-free reinterpret of a 64-bit pair as two floats
__device__ __forceinline__ float2 as_f2(u64 v) {
    float2 f;
    memcpy(&f, &v, 8);
    return f;
}

// ---------------------------------------------------------------------------
// Kernel 1: bilinear grid-sample warp + fb + weight  -> guidance [B,3,H,W]
// ---------------------------------------------------------------------------
__global__ __launch_bounds__(256)
void guidance_kernel(const float* __restrict__ v02,
                     const float* __restrict__ v20,
                     float* __restrict__ guid)
{
    int idx = blockIdx.x * blockDim.x + threadIdx.x;
    if (idx >= Bn * HW) return;
    int x = idx % Wn;
    int y = (idx / Wn) % Hn;
    int b = idx / HW;

    const float* v02b = v02 + b * 2 * HW;
    const float* v20b = v20 + b * 2 * HW;

    float f0 = v02b[y * Wn + x];
    float f1 = v02b[HW + y * Wn + x];

    float gx = -1.0f + 2.0f * (float)x / (float)(Wn - 1);
    float gy = -1.0f + 2.0f * (float)y / (float)(Hn - 1);
    float sgx = gx + f0 / (Wn * 0.5f);
    float sgy = gy + f1 / (Hn * 0.5f);

    float ix = (sgx + 1.0f) * 0.5f * (float)(Wn - 1);
    float iy = (sgy + 1.0f) * 0.5f * (float)(Hn - 1);

    float x0f = floorf(ix);
    float y0f = floorf(iy);
    int   x0  = (int)x0f;
    int   y0  = (int)y0f;
    float wx1 = ix - x0f;
    float wy1 = iy - y0f;
    float wx0 = 1.0f - wx1;
    float wy0 = 1.0f - wy1;

    float s0 = 0.0f, s1 = 0.0f;
#pragma unroll
    for (int cy = 0; cy < 2; cy++) {
        int   yc = y0 + cy;
        float wy = cy ? wy1 : wy0;
        bool  vy = (yc >= 0) && (yc <= Hn - 1);
        int   yi = min(max(yc, 0), Hn - 1);
#pragma unroll
        for (int cx = 0; cx < 2; cx++) {
            int   xc = x0 + cx;
            float wx = cx ? wx1 : wx0;
            bool  vx = (xc >= 0) && (xc <= Wn - 1);
            int   xi = min(max(xc, 0), Wn - 1);
            float wgt = (vx && vy) ? (wx * wy) : 0.0f;
            s0 += wgt * v20b[yi * Wn + xi];
            s1 += wgt * v20b[HW + yi * Wn + xi];
        }
    }

    float fb0 = f0 + s0;
    float fb1 = f1 + s1;
    float cons = sqrtf(fb0 * fb0 + fb1 * fb1);
    float wv = expf(-cons);

    float* gb = guid + b * 3 * HW;
    gb[y * Wn + x]          = fb0;
    gb[HW + y * Wn + x]     = fb1;
    gb[2 * HW + y * Wn + x] = wv;
}

// ---------------------------------------------------------------------------
// Kernel 2: fused conv3x3(3->32)+ReLU + conv1x1(32->50) + dynamic 5x5 apply.
// 2 pixels per thread.  Direct-form W2 with hidden-channel-pair packing:
//   ker(k,px) = b2[k] + sum_{c'} (w2[k,2c'],w2[k,2c'+1]) . (h[2c'],h[2c'+1])
// Both fma2 operands are MOV-free: weight pairs are adjacent in row-major w2
// (plain smem copy, LDS.128 = 2 pairs); h pairs are the natural conv3x3
// accumulator layout kept as register pairs through ReLU.
// ---------------------------------------------------------------------------
__global__ __launch_bounds__(NTHREADS, 4)
void refine_kernel(const float* __restrict__ v02,
                   const float* __restrict__ guid,
                   const float* __restrict__ w1,
                   const float* __restrict__ b1,
                   const float* __restrict__ w2,
                   const float* __restrict__ b2,
                   float* __restrict__ out)
{
    // W1 interleaved channel pairs: [c][jp][10 s-pairs]; pair s = (w1[2jp][c][s], w1[2jp+1][c][s])
    __shared__ __align__(16) float sW1p[3 * 16 * 20];
    __shared__ __align__(8)  float sB1p[HIDc];          // (b1[2jp],b1[2jp+1])
    // W2 plain row-major copy [50][32] — adjacent c's form the fma2 pairs
    __shared__ __align__(16) float sW2[OC * HIDc];
    // Bias pairs (b2[k], 0) for chain init
    __shared__ __align__(8) u64 sB2z[OC];
    // Guidance tile, DUPLICATED pairs (g,g): [3][GH][GW]
    __shared__ __align__(8) u64 sGp[3 * GH * GW];
    // Flow tile, channel pairs (flow0,flow1): [FH][FW]
    __shared__ __align__(8) u64 sFp[FH * FW];

    const int tid = threadIdx.y * TX + threadIdx.x;
    const int bx = blockIdx.x * TX;
    const int by = blockIdx.y * TYP;
    const int b  = blockIdx.z;

    // --- stage W1 pairs ---  w1 global: [j][c][s] -> j*27 + c*9 + s
    for (int i = tid; i < 3 * 16 * 10; i += NTHREADS) {
        int s  = i % 10;
        int jp = (i / 10) % 16;
        int c  = i / 160;
        float lo = 0.0f, hi = 0.0f;
        if (s < 9) {
            lo = w1[(2 * jp) * 27 + c * 9 + s];
            hi = w1[(2 * jp + 1) * 27 + c * 9 + s];
        }
        sW1p[i * 2]     = lo;
        sW1p[i * 2 + 1] = hi;
    }
    if (tid < 16) {
        sB1p[tid * 2]     = b1[2 * tid];
        sB1p[tid * 2 + 1] = b1[2 * tid + 1];
    }
    // --- stage W2: plain copy (vectorized) ---
    {
        const float4* src = (const float4*)w2;
        float4* dst = (float4*)sW2;
        for (int i = tid; i < OC * HIDc / 4; i += NTHREADS)
            dst[i] = src[i];
    }
    if (tid < OC) sB2z[tid] = pk2(b2[tid], 0.0f);

    // --- stage guidance tile as duplicated pairs (zero OOB = conv padding) ---
    const float* gb = guid + b * 3 * HW;
    for (int i = tid; i < 3 * GH * GW; i += NTHREADS) {
        int c  = i / (GH * GW);
        int r  = i - c * (GH * GW);
        int yy = r / GW;
        int xx = r - yy * GW;
        int gyy = by + yy - 1;
        int gxx = bx + xx - 1;
        float v = 0.0f;
        if (gyy >= 0 && gyy < Hn && gxx >= 0 && gxx < Wn)
            v = gb[c * HW + gyy * Wn + gxx];
        sGp[i] = pk2(v, v);
    }

    // --- stage flow tile as channel pairs (zero OOB = unfold padding) ---
    const float* fbase = v02 + b * 2 * HW;
    for (int i = tid; i < FH * FW; i += NTHREADS) {
        int yy = i / FW;
        int xx = i - yy * FW;
        int gyy = by + yy - 2;
        int gxx = bx + xx - 2;
        float f0 = 0.0f, f1 = 0.0f;
        if (gyy >= 0 && gyy < Hn && gxx >= 0 && gxx < Wn) {
            f0 = fbase[gyy * Wn + gxx];
            f1 = fbase[HW + gyy * Wn + gxx];
        }
        sFp[i] = pk2(f0, f1);
    }

    __syncthreads();

    const int lx = threadIdx.x;
    const int py = threadIdx.y * 2;   // tile-local row of pixel0 (pixel1 = py+1)

    // --- conv3x3: A0[jp] = (h[2jp],h[2jp+1]) for pixel0; A1 for pixel1 ---
    u64 A0[16], A1[16];
    {
        const u64* bp = (const u64*)sB1p;
#pragma unroll
        for (int jp = 0; jp < 16; jp++) { A0[jp] = bp[jp]; A1[jp] = bp[jp]; }
    }

#pragma unroll
    for (int c = 0; c < 3; c++) {
        // duplicated taps: 4 rows x 3 cols union of both pixels (direct LDS.64)
        u64 gd[12];
#pragma unroll
        for (int dy = 0; dy < 4; dy++)
#pragma unroll
            for (int dx = 0; dx < 3; dx++)
                gd[dy * 3 + dx] = sGp[c * (GH * GW) + (py + dy) * GW + (lx + dx)];

#pragma unroll
        for (int jp = 0; jp < 16; jp++) {
            const float* base = sW1p + (c * 16 + jp) * 20;
            ulonglong2 wA = *(const ulonglong2*)(base);        // s0,s1
            ulonglong2 wB = *(const ulonglong2*)(base + 4);    // s2,s3
            ulonglong2 wC = *(const ulonglong2*)(base + 8);    // s4,s5
            ulonglong2 wD = *(const ulonglong2*)(base + 12);   // s6,s7
            u64        wE = *(const u64*)(base + 16);          // s8
            A0[jp] = fma2(wA.x, gd[0], A0[jp]);  A1[jp] = fma2(wA.x, gd[3], A1[jp]);
            A0[jp] = fma2(wA.y, gd[1], A0[jp]);  A1[jp] = fma2(wA.y, gd[4], A1[jp]);
            A0[jp] = fma2(wB.x, gd[2], A0[jp]);  A1[jp] = fma2(wB.x, gd[5], A1[jp]);
            A0[jp] = fma2(wB.y, gd[3], A0[jp]);  A1[jp] = fma2(wB.y, gd[6], A1[jp]);
            A0[jp] = fma2(wC.x, gd[4], A0[jp]);  A1[jp] = fma2(wC.x, gd[7], A1[jp]);
            A0[jp] = fma2(wC.y, gd[5], A0[jp]);  A1[jp] = fma2(wC.y, gd[8], A1[jp]);
            A0[jp] = fma2(wD.x, gd[6], A0[jp]);  A1[jp] = fma2(wD.x, gd[9], A1[jp]);
            A0[jp] = fma2(wD.y, gd[7], A0[jp]);  A1[jp] = fma2(wD.y, gd[10], A1[jp]);
            A0[jp] = fma2(wE,   gd[8], A0[jp]);  A1[jp] = fma2(wE,   gd[11], A1[jp]);
        }
    }

    // ReLU halves and KEEP as pairs: hp[jp] = (relu(h[2jp]), relu(h[2jp+1]))
    u64 hp0[16], hp1[16];
#pragma unroll
    for (int jp = 0; jp < 16; jp++) {
        float2 a = as_f2(A0[jp]);
        hp0[jp] = pk2(fmaxf(a.x, 0.0f), fmaxf(a.y, 0.0f));
        float2 bb = as_f2(A1[jp]);
        hp1[jp] = pk2(fmaxf(bb.x, 0.0f), fmaxf(bb.y, 0.0f));
    }

    // --- 1x1 conv (direct form) + dynamic-kernel apply ---
    // ker(k,px) = b2[k] + w2[k,:].h(px);  out_ch(px) += ker(k,px) * patch
    float o00 = 0.0f, o10 = 0.0f;   // pixel0: ch0, ch1
    float o01 = 0.0f, o11 = 0.0f;   // pixel1: ch0, ch1

#pragma unroll 1
    for (int ki = 0; ki < KK; ki++) {
#pragma unroll
        for (int kj = 0; kj < KK; kj++) {
            int k = ki * KK + kj;
            // chains init = (b2, 0); horizontal add merges bias at the end
            u64 bz0 = sB2z[k];
            u64 bz1 = sB2z[NK + k];
            u64 t00 = bz0, t01 = bz0;     // ch0: px0, px1
            u64 t10 = bz1, t11 = bz1;     // ch1: px0, px1

            const ulonglong2* w0 = (const ulonglong2*)(sW2 + k * HIDc);
            const ulonglong2* w1r = (const ulonglong2*)(sW2 + (NK + k) * HIDc);
#pragma unroll
            for (int q = 0; q < 8; q++) {      // pairs 2q, 2q+1
                ulonglong2 wa = w0[q];
                ulonglong2 wb = w1r[q];
                t00 = fma2(wa.x, hp0[2 * q], t00);
                t01 = fma2(wa.x, hp1[2 * q], t01);
                t10 = fma2(wb.x, hp0[2 * q], t10);
                t11 = fma2(wb.x, hp1[2 * q], t11);
                t00 = fma2(wa.y, hp0[2 * q + 1], t00);
                t01 = fma2(wa.y, hp1[2 * q + 1], t01);
                t10 = fma2(wb.y, hp0[2 * q + 1], t10);
                t11 = fma2(wb.y, hp1[2 * q + 1], t11);
            }

            float2 a00 = as_f2(t00);
            float2 a01 = as_f2(t01);
            float2 a10 = as_f2(t10);
            float2 a11 = as_f2(t11);
            float ker00 = a00.x + a00.y;   // ch0, px0 (bias included)
            float ker01 = a01.x + a01.y;   // ch0, px1
            float ker10 = a10.x + a10.y;   // ch1, px0
            float ker11 = a11.x + a11.y;   // ch1, px1

            float2 p0 = as_f2(sFp[(py + ki) * FW + (lx + kj)]);       // (flow0,flow1) px0
            float2 p1 = as_f2(sFp[(py + 1 + ki) * FW + (lx + kj)]);   // px1
            o00 = fmaf(ker00, p0.x, o00);
            o10 = fmaf(ker10, p0.y, o10);
            o01 = fmaf(ker01, p1.x, o01);
            o11 = fmaf(ker11, p1.y, o11);
        }
    }

    int oy = by + py;
    int ox = bx + lx;
    float* ob = out + b * 2 * HW;
    ob[oy * Wn + ox]            = o00;
    ob[HW + oy * Wn + ox]       = o10;
    ob[(oy + 1) * Wn + ox]      = o01;
    ob[HW + (oy + 1) * Wn + ox] = o11;
}

// ---------------------------------------------------------------------------
// Launch
// ---------------------------------------------------------------------------
extern "C" void kernel_launch(void* const* d_in, const int* in_sizes, int n_in,
                              void* d_out, int out_size)
{
    const float* v02 = (const float*)d_in[0];
    const float* v20 = (const float*)d_in[1];
    const float* w1  = (const float*)d_in[2];
    const float* b1  = (const float*)d_in[3];
    const float* w2  = (const float*)d_in[4];
    const float* b2  = (const float*)d_in[5];
    float* out = (float*)d_out;

    float* guid;
    cudaGetSymbolAddress((void**)&guid, g_guid);

    {
        int total = Bn * HW;
        int threads = 256;
        int blocks = (total + threads - 1) / threads;
        guidance_kernel<<<blocks, threads>>>(v02, v20, guid);
    }
    {
        dim3 block(TX, TYT, 1);
        dim3 grid(Wn / TX, Hn / TYP, Bn);
        refine_kernel<<<grid, block>>>(v02, guid, w1, b1, w2, b2, out);
    }
}

// round 10
// speedup vs baseline: 1.2784x; 1.0478x over previous
#include <cuda_runtime.h>
#include <math.h>
#include <string.h>

// Problem constants
#define Bn  8
#define Hn  512
#define Wn  512
#define KK  5
#define NK  25      // KK*KK
#define HIDc 32
#define OC  50      // 2*NK

#define HW (Hn*Wn)

// Tile config: 32x8 pixel tile, 32x4 threads, 2 vertical pixels per thread.
#define TX 32
#define TYT 4
#define TYP 8
#define NTHREADS (TX*TYT)  // 128

#define GW (TX + 2)
#define GH (TYP + 2)
#define FW (TX + 4)
#define FH (TYP + 4)

typedef unsigned long long u64;

// ---------------------------------------------------------------------------
// packed f32x2 helpers
// ---------------------------------------------------------------------------
__device__ __forceinline__ u64 pk2(float lo, float hi) {
    u64 r;
    asm("mov.b64 %0, {%1,%2};" : "=l"(r) : "f"(lo), "f"(hi));
    return r;
}
__device__ __forceinline__ u64 fma2(u64 a, u64 b, u64 c) {
    u64 d;
    asm("fma.rn.f32x2 %0, %1, %2, %3;" : "=l"(d) : "l"(a), "l"(b), "l"(c));
    return d;
}
// MOV-free reinterpret of a 64-bit pair as two floats
__device__ __forceinline__ float2 as_f2(u64 v) {
    float2 f;
    memcpy(&f, &v, 8);
    return f;
}

// ---------------------------------------------------------------------------
// Single fused kernel:
//   per-tile guidance (bilinear grid-sample warp + fb + exp weight, recomputed
//   with halo) -> conv3x3(3->32)+ReLU -> conv1x1(32->50) as direct-form
//   hidden-channel-pair FFMA2 -> dynamic 5x5 kernel apply.
// 2 pixels per thread; all heavy fma2 operands MOV-free from smem/registers.
// ---------------------------------------------------------------------------
__global__ __launch_bounds__(NTHREADS, 5)
void refine_kernel(const float* __restrict__ v02,
                   const float* __restrict__ v20,
                   const float* __restrict__ w1,
                   const float* __restrict__ b1,
                   const float* __restrict__ w2,
                   const float* __restrict__ b2,
                   float* __restrict__ out)
{
    // W1 interleaved channel pairs: [c][jp][10 s-pairs]; pair s = (w1[2jp][c][s], w1[2jp+1][c][s])
    __shared__ __align__(16) float sW1p[3 * 16 * 20];
    __shared__ __align__(8)  float sB1p[HIDc];          // (b1[2jp],b1[2jp+1])
    // W2 plain row-major copy [50][32] — adjacent c's form the fma2 pairs
    __shared__ __align__(16) float sW2[OC * HIDc];
    // Bias pairs (b2[k], 0) for chain init
    __shared__ __align__(8) u64 sB2z[OC];
    // Guidance tile, DUPLICATED pairs (g,g): [3][GH][GW]
    __shared__ __align__(8) u64 sGp[3 * GH * GW];
    // Flow tile, channel pairs (flow0,flow1): [FH][FW]
    __shared__ __align__(8) u64 sFp[FH * FW];

    const int tid = threadIdx.y * TX + threadIdx.x;
    const int bx = blockIdx.x * TX;
    const int by = blockIdx.y * TYP;
    const int b  = blockIdx.z;

    // --- stage W1 pairs ---  w1 global: [j][c][s] -> j*27 + c*9 + s
    for (int i = tid; i < 3 * 16 * 10; i += NTHREADS) {
        int s  = i % 10;
        int jp = (i / 10) % 16;
        int c  = i / 160;
        float lo = 0.0f, hi = 0.0f;
        if (s < 9) {
            lo = w1[(2 * jp) * 27 + c * 9 + s];
            hi = w1[(2 * jp + 1) * 27 + c * 9 + s];
        }
        sW1p[i * 2]     = lo;
        sW1p[i * 2 + 1] = hi;
    }
    if (tid < 16) {
        sB1p[tid * 2]     = b1[2 * tid];
        sB1p[tid * 2 + 1] = b1[2 * tid + 1];
    }
    // --- stage W2: plain copy (vectorized) ---
    {
        const float4* src = (const float4*)w2;
        float4* dst = (float4*)sW2;
        for (int i = tid; i < OC * HIDc / 4; i += NTHREADS)
            dst[i] = src[i];
    }
    if (tid < OC) sB2z[tid] = pk2(b2[tid], 0.0f);

    const float* v02b = v02 + b * 2 * HW;
    const float* v20b = v20 + b * 2 * HW;

    // --- compute guidance inline for the halo-1 tile (zero OOB = conv pad) ---
    for (int i = tid; i < GH * GW; i += NTHREADS) {
        int yy = i / GW;
        int xx = i - yy * GW;
        int gyy = by + yy - 1;
        int gxx = bx + xx - 1;
        float fb0 = 0.0f, fb1 = 0.0f, wv = 0.0f;
        if (gyy >= 0 && gyy < Hn && gxx >= 0 && gxx < Wn) {
            float f0 = v02b[gyy * Wn + gxx];
            float f1 = v02b[HW + gyy * Wn + gxx];

            float gx = -1.0f + 2.0f * (float)gxx / (float)(Wn - 1);
            float gy = -1.0f + 2.0f * (float)gyy / (float)(Hn - 1);
            float sgx = gx + f0 / (Wn * 0.5f);
            float sgy = gy + f1 / (Hn * 0.5f);

            float ixf = (sgx + 1.0f) * 0.5f * (float)(Wn - 1);
            float iyf = (sgy + 1.0f) * 0.5f * (float)(Hn - 1);

            float x0f = floorf(ixf);
            float y0f = floorf(iyf);
            int   x0  = (int)x0f;
            int   y0  = (int)y0f;
            float wx1 = ixf - x0f;
            float wy1 = iyf - y0f;
            float wx0 = 1.0f - wx1;
            float wy0 = 1.0f - wy1;

            float s0 = 0.0f, s1 = 0.0f;
#pragma unroll
            for (int cy = 0; cy < 2; cy++) {
                int   yc = y0 + cy;
                float wy = cy ? wy1 : wy0;
                bool  vy = (yc >= 0) && (yc <= Hn - 1);
                int   yi = min(max(yc, 0), Hn - 1);
#pragma unroll
                for (int cx = 0; cx < 2; cx++) {
                    int   xc = x0 + cx;
                    float wx = cx ? wx1 : wx0;
                    bool  vx = (xc >= 0) && (xc <= Wn - 1);
                    int   xi = min(max(xc, 0), Wn - 1);
                    float wgt = (vx && vy) ? (wx * wy) : 0.0f;
                    s0 += wgt * v20b[yi * Wn + xi];
                    s1 += wgt * v20b[HW + yi * Wn + xi];
                }
            }
            fb0 = f0 + s0;
            fb1 = f1 + s1;
            float cons = sqrtf(fb0 * fb0 + fb1 * fb1);
            wv = __expf(-cons);
        }
        sGp[0 * (GH * GW) + i] = pk2(fb0, fb0);
        sGp[1 * (GH * GW) + i] = pk2(fb1, fb1);
        sGp[2 * (GH * GW) + i] = pk2(wv, wv);
    }

    // --- stage flow tile as channel pairs (zero OOB = unfold padding) ---
    for (int i = tid; i < FH * FW; i += NTHREADS) {
        int yy = i / FW;
        int xx = i - yy * FW;
        int gyy = by + yy - 2;
        int gxx = bx + xx - 2;
        float f0 = 0.0f, f1 = 0.0f;
        if (gyy >= 0 && gyy < Hn && gxx >= 0 && gxx < Wn) {
            f0 = v02b[gyy * Wn + gxx];
            f1 = v02b[HW + gyy * Wn + gxx];
        }
        sFp[i] = pk2(f0, f1);
    }

    __syncthreads();

    const int lx = threadIdx.x;
    const int py = threadIdx.y * 2;   // tile-local row of pixel0 (pixel1 = py+1)

    // --- conv3x3: A0[jp] = (h[2jp],h[2jp+1]) for pixel0; A1 for pixel1 ---
    u64 A0[16], A1[16];
    {
        const u64* bp = (const u64*)sB1p;
#pragma unroll
        for (int jp = 0; jp < 16; jp++) { A0[jp] = bp[jp]; A1[jp] = bp[jp]; }
    }

#pragma unroll
    for (int c = 0; c < 3; c++) {
        // duplicated taps: 4 rows x 3 cols union of both pixels (direct LDS.64)
        u64 gd[12];
#pragma unroll
        for (int dy = 0; dy < 4; dy++)
#pragma unroll
            for (int dx = 0; dx < 3; dx++)
                gd[dy * 3 + dx] = sGp[c * (GH * GW) + (py + dy) * GW + (lx + dx)];

#pragma unroll
        for (int jp = 0; jp < 16; jp++) {
            const float* base = sW1p + (c * 16 + jp) * 20;
            ulonglong2 wA = *(const ulonglong2*)(base);        // s0,s1
            ulonglong2 wB = *(const ulonglong2*)(base + 4);    // s2,s3
            ulonglong2 wC = *(const ulonglong2*)(base + 8);    // s4,s5
            ulonglong2 wD = *(const ulonglong2*)(base + 12);   // s6,s7
            u64        wE = *(const u64*)(base + 16);          // s8
            A0[jp] = fma2(wA.x, gd[0], A0[jp]);  A1[jp] = fma2(wA.x, gd[3], A1[jp]);
            A0[jp] = fma2(wA.y, gd[1], A0[jp]);  A1[jp] = fma2(wA.y, gd[4], A1[jp]);
            A0[jp] = fma2(wB.x, gd[2], A0[jp]);  A1[jp] = fma2(wB.x, gd[5], A1[jp]);
            A0[jp] = fma2(wB.y, gd[3], A0[jp]);  A1[jp] = fma2(wB.y, gd[6], A1[jp]);
            A0[jp] = fma2(wC.x, gd[4], A0[jp]);  A1[jp] = fma2(wC.x, gd[7], A1[jp]);
            A0[jp] = fma2(wC.y, gd[5], A0[jp]);  A1[jp] = fma2(wC.y, gd[8], A1[jp]);
            A0[jp] = fma2(wD.x, gd[6], A0[jp]);  A1[jp] = fma2(wD.x, gd[9], A1[jp]);
            A0[jp] = fma2(wD.y, gd[7], A0[jp]);  A1[jp] = fma2(wD.y, gd[10], A1[jp]);
            A0[jp] = fma2(wE,   gd[8], A0[jp]);  A1[jp] = fma2(wE,   gd[11], A1[jp]);
        }
    }

    // ReLU halves and KEEP as pairs: hp[jp] = (relu(h[2jp]), relu(h[2jp+1]))
    u64 hp0[16], hp1[16];
#pragma unroll
    for (int jp = 0; jp < 16; jp++) {
        float2 a = as_f2(A0[jp]);
        hp0[jp] = pk2(fmaxf(a.x, 0.0f), fmaxf(a.y, 0.0f));
        float2 bb = as_f2(A1[jp]);
        hp1[jp] = pk2(fmaxf(bb.x, 0.0f), fmaxf(bb.y, 0.0f));
    }

    // --- 1x1 conv (direct form) + dynamic-kernel apply ---
    // ker(k,px) = b2[k] + w2[k,:].h(px);  out_ch(px) += ker(k,px) * patch
    float o00 = 0.0f, o10 = 0.0f;   // pixel0: ch0, ch1
    float o01 = 0.0f, o11 = 0.0f;   // pixel1: ch0, ch1

#pragma unroll 1
    for (int ki = 0; ki < KK; ki++) {
#pragma unroll
        for (int kj = 0; kj < KK; kj++) {
            int k = ki * KK + kj;
            // chains init = (b2, 0); horizontal add merges bias at the end
            u64 bz0 = sB2z[k];
            u64 bz1 = sB2z[NK + k];
            u64 t00 = bz0, t01 = bz0;     // ch0: px0, px1
            u64 t10 = bz1, t11 = bz1;     // ch1: px0, px1

            const ulonglong2* w0 = (const ulonglong2*)(sW2 + k * HIDc);
            const ulonglong2* w1r = (const ulonglong2*)(sW2 + (NK + k) * HIDc);
#pragma unroll
            for (int q = 0; q < 8; q++) {      // pairs 2q, 2q+1
                ulonglong2 wa = w0[q];
                ulonglong2 wb = w1r[q];
                t00 = fma2(wa.x, hp0[2 * q], t00);
                t01 = fma2(wa.x, hp1[2 * q], t01);
                t10 = fma2(wb.x, hp0[2 * q], t10);
                t11 = fma2(wb.x, hp1[2 * q], t11);
                t00 = fma2(wa.y, hp0[2 * q + 1], t00);
                t01 = fma2(wa.y, hp1[2 * q + 1], t01);
                t10 = fma2(wb.y, hp0[2 * q + 1], t10);
                t11 = fma2(wb.y, hp1[2 * q + 1], t11);
            }

            float2 a00 = as_f2(t00);
            float2 a01 = as_f2(t01);
            float2 a10 = as_f2(t10);
            float2 a11 = as_f2(t11);
            float ker00 = a00.x + a00.y;   // ch0, px0 (bias included)
            float ker01 = a01.x + a01.y;   // ch0, px1
            float ker10 = a10.x + a10.y;   // ch1, px0
            float ker11 = a11.x + a11.y;   // ch1, px1

            float2 p0 = as_f2(sFp[(py + ki) * FW + (lx + kj)]);       // (flow0,flow1) px0
            float2 p1 = as_f2(sFp[(py + 1 + ki) * FW + (lx + kj)]);   // px1
            o00 = fmaf(ker00, p0.x, o00);
            o10 = fmaf(ker10, p0.y, o10);
            o01 = fmaf(ker01, p1.x, o01);
            o11 = fmaf(ker11, p1.y, o11);
        }
    }

    int oy = by + py;
    int ox = bx + lx;
    float* ob = out + b * 2 * HW;
    ob[oy * Wn + ox]            = o00;
    ob[HW + oy * Wn + ox]       = o10;
    ob[(oy + 1) * Wn + ox]      = o01;
    ob[HW + (oy + 1) * Wn + ox] = o11;
}

// ---------------------------------------------------------------------------
// Launch
// ---------------------------------------------------------------------------
extern "C" void kernel_launch(void* const* d_in, const int* in_sizes, int n_in,
                              void* d_out, int out_size)
{
    const float* v02 = (const float*)d_in[0];
    const float* v20 = (const float*)d_in[1];
    const float* w1  = (const float*)d_in[2];
    const float* b1  = (const float*)d_in[3];
    const float* w2  = (const float*)d_in[4];
    const float* b2  = (const float*)d_in[5];
    float* out = (float*)d_out;

    dim3 block(TX, TYT, 1);
    dim3 grid(Wn / TX, Hn / TYP, Bn);
    refine_kernel<<<grid, block>>>(v02, v20, w1, b1, w2, b2, out);
}